// round 1
// baseline (speedup 1.0000x reference)
#include <cuda_runtime.h>
#include <math.h>

#define BB 8
#define SS 256
#define HH 100
#define PP 20
#define EPSF 1e-8f
#define NEGF 1e30f

// ---------------- scratch (static device globals; no runtime allocation) ----
__device__ float g_c[2][BB][SS][HH];        // masked contexts (0=p,1=h)
__device__ float g_norm[2][BB][SS];         // row L2 norms
__device__ float g_npw[2][BB][SS][4*PP];    // weighted row norms per weight-set
__device__ float g_w2[4][PP][HH];           // squared weights (full,maxpool,att,maxatt)
__device__ float g_last[2][BB][HH];         // last valid token rows
__device__ float g_nlast[2][BB];
__device__ float g_nlastw[2][BB][PP];       // w_full weighted norms of last rows
__device__ float g_len[2][BB];
__device__ float g_cos[BB][SS][SS];
__device__ float g_cosT[BB][SS][SS];
__device__ float g_cmax[2][BB][SS];
__device__ float g_cmean[2][BB][SS];
__device__ float g_csum[2][BB][SS];
__device__ float g_attmean[2][BB][SS][HH];
__device__ float g_attmax[2][BB][SS][HH];
__device__ float g_mpmax[2][BB][SS][PP];
__device__ float g_mpmean[2][BB][SS][PP];

// ---------------- K0: squared weights ---------------------------------------
__global__ void k_w2(const float* wf, const float* wm, const float* wa, const float* wx) {
    const float* w = (blockIdx.x == 0) ? wf : (blockIdx.x == 1) ? wm
                    : (blockIdx.x == 2) ? wa : wx;
    for (int idx = threadIdx.x; idx < PP * HH; idx += blockDim.x) {
        float v = w[idx];
        (&g_w2[blockIdx.x][0][0])[idx] = v * v;
    }
}

// ---------------- K1: mask, norms, weighted norms ----------------------------
__global__ void k_prep(const float* cp, const int* mp, const float* ch, const int* mh) {
    int side = blockIdx.y;
    int r = blockIdx.x, b = r / SS, i = r % SS;
    const float* ctx = side ? ch : cp;
    const int* msk = side ? mh : mp;
    int t = threadIdx.x;
    __shared__ float sx2[HH];
    float m = msk[r] ? 1.f : 0.f;
    if (t < HH) {
        float x = ctx[r * HH + t] * m;
        g_c[side][b][i][t] = x;
        sx2[t] = x * x;
    }
    __syncthreads();
    if (t < 4 * PP) {
        int ws = t / PP, p = t % PP;
        float s = 0.f;
        for (int h = 0; h < HH; h++) s += g_w2[ws][p][h] * sx2[h];
        g_npw[side][b][i][t] = sqrtf(s);
    }
    if (t == 96) {
        float s = 0.f;
        for (int h = 0; h < HH; h++) s += sx2[h];
        g_norm[side][b][i] = sqrtf(s);
    }
}

// ---------------- K2: lengths + last valid token -----------------------------
__global__ void k_last(const int* mp, const int* mh) {
    int side = blockIdx.y, b = blockIdx.x, t = threadIdx.x;
    const int* msk = side ? mh : mp;
    __shared__ int sred[128];
    __shared__ int sidx;
    int s = 0;
    for (int j = t; j < SS; j += 128) s += msk[b * SS + j];
    sred[t] = s;
    __syncthreads();
    if (t == 0) {
        int tot = 0;
        for (int k = 0; k < 128; k++) tot += sred[k];
        g_len[side][b] = (float)tot;
        sidx = (tot > 0) ? (tot - 1) : 0;
    }
    __syncthreads();
    int idx = sidx;
    if (t < HH) g_last[side][b][t] = g_c[side][b][idx][t];
    if (t < PP) g_nlastw[side][b][t] = g_npw[side][b][idx][t];  // w_full slot
    if (t == 127) g_nlast[side][b] = g_norm[side][b][idx];
}

// ---------------- K3: pairwise cosine (32x32 smem tiles) ---------------------
__global__ void k_cos() {
    int b = blockIdx.x, it = blockIdx.y, jt = blockIdx.z;
    __shared__ float sa[32][101], sb[32][101];
    __shared__ float sni[32], snj[32];
    int t = threadIdx.x;
    const float* ap = &g_c[0][b][it * 32][0];
    const float* bp = &g_c[1][b][jt * 32][0];
    for (int idx = t; idx < 32 * HH; idx += 256) {
        int r = idx / HH, h = idx % HH;
        sa[r][h] = ap[idx];
        sb[r][h] = bp[idx];
    }
    if (t < 32) {
        sni[t] = 1.f / fmaxf(g_norm[0][b][it * 32 + t], EPSF);
        snj[t] = 1.f / fmaxf(g_norm[1][b][jt * 32 + t], EPSF);
    }
    __syncthreads();
    int tx = t & 15, ty = t >> 4;
    float a00 = 0, a01 = 0, a10 = 0, a11 = 0;
    for (int h = 0; h < HH; h++) {
        float x0 = sa[ty * 2][h], x1 = sa[ty * 2 + 1][h];
        float y0 = sb[tx * 2][h], y1 = sb[tx * 2 + 1][h];
        a00 = fmaf(x0, y0, a00);
        a01 = fmaf(x0, y1, a01);
        a10 = fmaf(x1, y0, a10);
        a11 = fmaf(x1, y1, a11);
    }
    int i0 = it * 32 + ty * 2, j0 = jt * 32 + tx * 2;
    float c;
    c = a00 * sni[ty * 2] * snj[tx * 2];         g_cos[b][i0][j0] = c;     g_cosT[b][j0][i0] = c;
    c = a01 * sni[ty * 2] * snj[tx * 2 + 1];     g_cos[b][i0][j0 + 1] = c; g_cosT[b][j0 + 1][i0] = c;
    c = a10 * sni[ty * 2 + 1] * snj[tx * 2];     g_cos[b][i0 + 1][j0] = c; g_cosT[b][j0][i0 + 1] = c;
    c = a11 * sni[ty * 2 + 1] * snj[tx * 2 + 1]; g_cos[b][i0 + 1][j0 + 1] = c; g_cosT[b][j0 + 1][i0 + 1] = c;
}

// ---------------- K4: row reductions of cos (max / mean / sum) ---------------
__global__ void k_rowred(const int* mp, const int* mh) {
    int side = blockIdx.z, b = blockIdx.y, r = blockIdx.x, t = threadIdx.x;
    const float* row = side ? &g_cosT[b][r][0] : &g_cos[b][r][0];
    const int* omsk = side ? mp : mh;
    float v = row[t];
    float mv = omsk[b * SS + t] ? v : -NEGF;
    __shared__ float sm[256], ss[256];
    sm[t] = mv;
    ss[t] = v;
    __syncthreads();
    for (int o = 128; o; o >>= 1) {
        if (t < o) {
            sm[t] = fmaxf(sm[t], sm[t + o]);
            ss[t] += ss[t + o];
        }
        __syncthreads();
    }
    if (t == 0) {
        g_cmax[side][b][r] = sm[0];
        g_csum[side][b][r] = ss[0];
        g_cmean[side][b][r] = ss[0] / fmaxf(g_len[1 - side][b], EPSF);
    }
}

// ---------------- K5: attentive mean + max attentive vectors -----------------
__global__ void k_att(const int* mp, const int* mh) {
    int side = blockIdx.z, b = blockIdx.y, i = blockIdx.x, t = threadIdx.x;
    __shared__ float satt[SS];
    __shared__ float sbias[SS];
    const float* row = side ? &g_cosT[b][i][0] : &g_cos[b][i][0];
    const int* omsk = side ? mp : mh;
    for (int j = t; j < SS; j += 128) {
        satt[j] = row[j];
        sbias[j] = omsk[b * SS + j] ? 0.f : -NEGF;
    }
    __syncthreads();
    if (t < HH) {
        const float* oc = &g_c[1 - side][b][0][0];
        float mean = 0.f, vmax = -NEGF;
        for (int j = 0; j < SS; j++) {
            float prod = satt[j] * oc[j * HH + t];
            mean += prod;
            vmax = fmaxf(vmax, prod + sbias[j]);
        }
        float denom = fmaxf(g_csum[side][b][i], EPSF);
        g_attmean[side][b][i][t] = mean / denom;
        g_attmax[side][b][i][t] = vmax;
    }
}

// ---------------- K6: maxpool pairwise multi-perspective (dominant GEMM) -----
__global__ void k_maxpool(const int* mp, const int* mh) {
    int p = blockIdx.x, b = blockIdx.y;
    int t = threadIdx.x;                 // 256 threads, thread == row i
    __shared__ float w2s[HH];
    __shared__ float chs[32 * HH];
    __shared__ float sinvh[32];
    __shared__ float sbias[32];
    __shared__ float wmax[8][32];
    __shared__ float wsum[8][32];

    if (t < HH) w2s[t] = g_w2[1][p][t];
    int i = t;
    float nprow = g_npw[0][b][i][PP + p];
    int maski = mp[b * SS + i];
    float invp = (maski && nprow > 0.f) ? 1.f / nprow : 0.f;
    float len_p = g_len[0][b], len_h = g_len[1][b];

    float pmax = -NEGF, psum = 0.f;
    const float* cprow = &g_c[0][b][i][0];
    int lane = t & 31, w = t >> 5;

    for (int jt = 0; jt < 8; jt++) {
        __syncthreads();
        {
            const float* src = &g_c[1][b][jt * 32][0];
            for (int idx = t; idx < 32 * HH; idx += 256) chs[idx] = src[idx];
            if (t < 32) {
                int j = jt * 32 + t;
                float n = g_npw[1][b][j][PP + p];
                int mj = mh[b * SS + j];
                sinvh[t] = (mj && n > 0.f) ? 1.f / n : 0.f;
                sbias[t] = mj ? 0.f : -NEGF;
            }
        }
        __syncthreads();

        float dots[32];
#pragma unroll
        for (int jj = 0; jj < 32; jj++) dots[jj] = 0.f;
        for (int h = 0; h < HH; h++) {
            float a = cprow[h] * w2s[h];
#pragma unroll
            for (int jj = 0; jj < 32; jj++)
                dots[jj] = fmaf(a, chs[jj * HH + h], dots[jj]);
        }

#pragma unroll
        for (int jj = 0; jj < 32; jj++) {
            float d = dots[jj];
            float v = d * sinvh[jj];          // 0 at masked j
            psum += v;
            pmax = fmaxf(pmax, v + sbias[jj]);
            float u = d * invp;               // 0 at masked i
            float um = maski ? u : -NEGF;
#pragma unroll
            for (int o = 16; o; o >>= 1) {
                um = fmaxf(um, __shfl_xor_sync(0xffffffffu, um, o));
                u += __shfl_xor_sync(0xffffffffu, u, o);
            }
            if (lane == 0) { wmax[w][jj] = um; wsum[w][jj] = u; }
        }
        __syncthreads();
        if (t < 32) {
            int j = jt * 32 + t;
            float hm = -NEGF, hs = 0.f;
#pragma unroll
            for (int ww = 0; ww < 8; ww++) {
                hm = fmaxf(hm, wmax[ww][t]);
                hs += wsum[ww][t];
            }
            g_mpmax[1][b][j][p] = hm * sinvh[t];
            g_mpmean[1][b][j][p] = hs * sinvh[t] / fmaxf(len_p, EPSF);
        }
    }
    g_mpmax[0][b][i][p] = pmax * invp;
    g_mpmean[0][b][i][p] = psum * invp / fmaxf(len_h, EPSF);
}

// ---------------- K7: assemble 105 outputs per (side,b,i) --------------------
__global__ void k_final(float* out) {
    int side = blockIdx.z, b = blockIdx.y, i = blockIdx.x, t = threadIdx.x;
    __shared__ float sx[HH], sL[HH], sva[HH], svm[HH], sred[105];
    if (t < HH) {
        sx[t] = g_c[side][b][i][t];
        sL[t] = g_last[1 - side][b][t];
        sva[t] = g_attmean[side][b][i][t];
        svm[t] = g_attmax[side][b][i][t];
    }
    __syncthreads();
    if (t < 105) {
        float s = 0.f;
        if (t == 0)      { for (int h = 0; h < HH; h++) s += sx[h] * sL[h]; }
        else if (t == 1) { for (int h = 0; h < HH; h++) s += sx[h] * sva[h]; }
        else if (t == 2) { for (int h = 0; h < HH; h++) s += sx[h] * svm[h]; }
        else if (t == 3) { for (int h = 0; h < HH; h++) s += sva[h] * sva[h]; }
        else if (t == 4) { for (int h = 0; h < HH; h++) s += svm[h] * svm[h]; }
        else if (t < 25) { int p = t - 5;  for (int h = 0; h < HH; h++) s += g_w2[0][p][h] * sx[h] * sL[h]; }
        else if (t < 45) { int p = t - 25; for (int h = 0; h < HH; h++) s += g_w2[2][p][h] * sx[h] * sva[h]; }
        else if (t < 65) { int p = t - 45; for (int h = 0; h < HH; h++) s += g_w2[2][p][h] * sva[h] * sva[h]; }
        else if (t < 85) { int p = t - 65; for (int h = 0; h < HH; h++) s += g_w2[3][p][h] * sx[h] * svm[h]; }
        else             { int p = t - 85; for (int h = 0; h < HH; h++) s += g_w2[3][p][h] * svm[h] * svm[h]; }
        sred[t] = s;
    }
    __syncthreads();
    if (t < 105) {
        float np = g_norm[side][b][i];
        float o;
        if (t == 0)      o = g_cmax[side][b][i];
        else if (t == 1) o = g_cmean[side][b][i];
        else if (t == 2) o = sred[0] / (fmaxf(np, EPSF) * fmaxf(g_nlast[1 - side][b], EPSF));
        else if (t < 23) {
            int p = t - 3;
            o = sred[5 + p] / (fmaxf(g_npw[side][b][i][p], EPSF) * fmaxf(g_nlastw[1 - side][b][p], EPSF));
        }
        else if (t < 43) o = g_mpmax[side][b][i][t - 23];
        else if (t < 63) o = g_mpmean[side][b][i][t - 43];
        else if (t == 63) o = sred[1] / (fmaxf(np, EPSF) * fmaxf(sqrtf(sred[3]), EPSF));
        else if (t < 84) {
            int p = t - 64;
            o = sred[25 + p] / (fmaxf(g_npw[side][b][i][2 * PP + p], EPSF) * fmaxf(sqrtf(sred[45 + p]), EPSF));
        }
        else if (t == 84) o = sred[2] / (fmaxf(np, EPSF) * fmaxf(sqrtf(sred[4]), EPSF));
        else {
            int p = t - 85;
            o = sred[65 + p] / (fmaxf(g_npw[side][b][i][3 * PP + p], EPSF) * fmaxf(sqrtf(sred[85 + p]), EPSF));
        }
        out[((size_t)(side * BB + b) * SS + i) * 105 + t] = o;
    }
}

// ---------------- launch ------------------------------------------------------
extern "C" void kernel_launch(void* const* d_in, const int* in_sizes, int n_in,
                              void* d_out, int out_size) {
    const float* ctx_p = (const float*)d_in[0];
    const int*   mp    = (const int*)d_in[1];
    const float* ctx_h = (const float*)d_in[2];
    const int*   mh    = (const int*)d_in[3];
    const float* wf    = (const float*)d_in[4];
    const float* wm    = (const float*)d_in[5];
    const float* wa    = (const float*)d_in[6];
    const float* wx    = (const float*)d_in[7];
    float* out = (float*)d_out;

    k_w2<<<4, 256>>>(wf, wm, wa, wx);
    k_prep<<<dim3(BB * SS, 2), 128>>>(ctx_p, mp, ctx_h, mh);
    k_last<<<dim3(BB, 2), 128>>>(mp, mh);
    k_cos<<<dim3(BB, 8, 8), 256>>>();
    k_rowred<<<dim3(SS, BB, 2), 256>>>(mp, mh);
    k_att<<<dim3(SS, BB, 2), 128>>>(mp, mh);
    k_maxpool<<<dim3(PP, BB), 256>>>(mp, mh);
    k_final<<<dim3(SS, BB, 2), 128>>>(out);
}